// round 1
// baseline (speedup 1.0000x reference)
#include <cuda_runtime.h>
#include <cstdint>
#include <cstdio>

// ---------------------------------------------------------------------------
// CGRU cell: h = z*h_tm1 + (1-z)*hh
//   PreZR_real/imag = [x|h] @ [[K];[R]] + bias   (gates z,r, K=8192)
//   Xh = x @ Kh + bh                             (gate h, K=4096)
//   rh = hard_sigmoid(Pre_r) * h_tm1
//   Hh = rh @ Rh                                 (K=4096)
//   hh = tanh(Xh + Hh)
// Complex matmul realized by K-segment routing into real/imag weight matrices
// with per-segment sign flips (real part: [Wr;Wi], imag part: [-Wi;Wr]).
// ---------------------------------------------------------------------------

#define LDA   4096
#define LDW   6144

// scratch (device globals: allocation inside kernel_launch is forbidden)
__device__ float g_PreR[1024 * 4096];
__device__ float g_PreI[1024 * 4096];
__device__ float g_XhR [1024 * 2048];
__device__ float g_XhI [1024 * 2048];
__device__ float g_HhR [1024 * 2048];
__device__ float g_HhI [1024 * 2048];
__device__ float g_RH  [1024 * 4096];

__device__ __forceinline__ unsigned f2tf32(float x) {
    unsigned u;
    asm("cvt.rna.tf32.f32 %0, %1;" : "=r"(u) : "f"(x));
    return u;
}

#define ASTR 36          // A smem row stride (floats), conflict-free + 16B aligned
#define BSTR 136         // B smem row stride (floats)
#define ASZ  (128 * ASTR)
#define BSZ  (32  * BSTR)

// C[1024 x N] = A[1024 x K] @ Bsel[K x N] (+bias), K = KT*32,
// B row k comes from Bseg[k>>11] with sign sseg[k>>11]; A row k from A0 (k<4096) else A1.
__global__ void __launch_bounds__(256, 1) gemm_tf32(
    const float* __restrict__ A0, const float* __restrict__ A1,
    const float* __restrict__ B0, const float* __restrict__ B1,
    const float* __restrict__ B2, const float* __restrict__ B3,
    unsigned s0, unsigned s1, unsigned s2, unsigned s3,
    int col0, int KT, const float* __restrict__ bias,
    float* __restrict__ C, int ldC)
{
    extern __shared__ unsigned smem[];
    unsigned* As = smem;              // 2 stages of [128][ASTR]
    unsigned* Bs = smem + 2 * ASZ;    // 2 stages of [32][BSTR]

    const int tid  = threadIdx.x;
    const int lane = tid & 31;
    const int warp = tid >> 5;
    const int wm   = warp >> 2;   // 0..1  (64-row warp tile)
    const int wn   = warp & 3;    // 0..3  (32-col warp tile)
    const int bm   = blockIdx.x;
    const int bn   = blockIdx.y;
    const int gid  = lane >> 2;   // groupID
    const int tig  = lane & 3;    // threadID_in_group

    float acc[4][4][4];
    #pragma unroll
    for (int i = 0; i < 4; i++)
        #pragma unroll
        for (int j = 0; j < 4; j++)
            #pragma unroll
            for (int k = 0; k < 4; k++) acc[i][j][k] = 0.f;

    // per-thread gmem load coords
    const int arow   = tid >> 3;   // + 32*i  -> 0..127
    const int ac4    = tid & 7;    // float4 col within 32-k tile
    const int brow_t = tid >> 5;   // + 8*i   -> 0..31
    const int bc4    = tid & 31;   // float4 col within 128-n tile

    float4 areg[4], breg[4];
    unsigned curSgn = 0, nextSgn = 0;

#define LOAD_TILE(KT_IDX)                                                          \
    do {                                                                           \
        int kg = (KT_IDX) * 32;                                                    \
        const float* Ap; int krel;                                                 \
        if (kg >= 4096) { Ap = A1; krel = kg - 4096; }                             \
        else            { Ap = A0; krel = kg; }                                    \
        const float* abase = Ap + (size_t)(bm * 128) * LDA + krel;                 \
        _Pragma("unroll")                                                          \
        for (int i = 0; i < 4; i++)                                                \
            areg[i] = *(const float4*)(abase + (size_t)(arow + 32 * i) * LDA + ac4 * 4); \
        int seg = kg >> 11;                                                        \
        const float* Bp = (seg == 0) ? B0 : (seg == 1) ? B1 : (seg == 2) ? B2 : B3;\
        nextSgn         = (seg == 0) ? s0 : (seg == 1) ? s1 : (seg == 2) ? s2 : s3;\
        const float* bbase = Bp + (size_t)(kg & 2047) * LDW + col0 + bn * 128 + bc4 * 4; \
        _Pragma("unroll")                                                          \
        for (int i = 0; i < 4; i++)                                                \
            breg[i] = *(const float4*)(bbase + (size_t)(brow_t + 8 * i) * LDW);    \
    } while (0)

    LOAD_TILE(0);
    curSgn = nextSgn;

    for (int kt = 0; kt < KT; ++kt) {
        unsigned* as = As + (kt & 1) * ASZ;
        unsigned* bs = Bs + (kt & 1) * BSZ;

        // convert + store current tile
        #pragma unroll
        for (int i = 0; i < 4; i++) {
            float4 v = areg[i];
            uint4 t;
            t.x = f2tf32(v.x); t.y = f2tf32(v.y); t.z = f2tf32(v.z); t.w = f2tf32(v.w);
            *(uint4*)(as + (arow + 32 * i) * ASTR + ac4 * 4) = t;
        }
        #pragma unroll
        for (int i = 0; i < 4; i++) {
            float4 v = breg[i];
            uint4 t;
            t.x = f2tf32(v.x) ^ curSgn; t.y = f2tf32(v.y) ^ curSgn;
            t.z = f2tf32(v.z) ^ curSgn; t.w = f2tf32(v.w) ^ curSgn;
            *(uint4*)(bs + (brow_t + 8 * i) * BSTR + bc4 * 4) = t;
        }
        __syncthreads();

        if (kt + 1 < KT) LOAD_TILE(kt + 1);

        // compute 128x128x32 from smem stage
        #pragma unroll
        for (int s = 0; s < 4; s++) {
            unsigned a[4][4];
            #pragma unroll
            for (int mf = 0; mf < 4; mf++) {
                const unsigned* ap = as + (wm * 64 + mf * 16 + gid) * ASTR + s * 8 + tig;
                a[mf][0] = ap[0];
                a[mf][1] = ap[8 * ASTR];
                a[mf][2] = ap[4];
                a[mf][3] = ap[8 * ASTR + 4];
            }
            unsigned b[4][2];
            #pragma unroll
            for (int nf = 0; nf < 4; nf++) {
                const unsigned* bp = bs + (s * 8 + tig) * BSTR + wn * 32 + nf * 8 + gid;
                b[nf][0] = bp[0];
                b[nf][1] = bp[4 * BSTR];
            }
            #pragma unroll
            for (int mf = 0; mf < 4; mf++)
                #pragma unroll
                for (int nf = 0; nf < 4; nf++) {
                    asm volatile(
                        "mma.sync.aligned.m16n8k8.row.col.f32.tf32.tf32.f32 "
                        "{%0,%1,%2,%3},{%4,%5,%6,%7},{%8,%9},{%0,%1,%2,%3};"
                        : "+f"(acc[mf][nf][0]), "+f"(acc[mf][nf][1]),
                          "+f"(acc[mf][nf][2]), "+f"(acc[mf][nf][3])
                        : "r"(a[mf][0]), "r"(a[mf][1]), "r"(a[mf][2]), "r"(a[mf][3]),
                          "r"(b[nf][0]), "r"(b[nf][1]));
                }
        }
        curSgn = nextSgn;
    }

    // epilogue: optional bias + store
    #pragma unroll
    for (int mf = 0; mf < 4; mf++) {
        int row = bm * 128 + wm * 64 + mf * 16 + gid;
        #pragma unroll
        for (int nf = 0; nf < 4; nf++) {
            int col = bn * 128 + wn * 32 + nf * 8 + tig * 2;
            float bb0 = 0.f, bb1 = 0.f;
            if (bias) { bb0 = bias[col]; bb1 = bias[col + 1]; }
            float2 v0 = make_float2(acc[mf][nf][0] + bb0, acc[mf][nf][1] + bb1);
            float2 v1 = make_float2(acc[mf][nf][2] + bb0, acc[mf][nf][3] + bb1);
            *(float2*)(C + (size_t)row       * ldC + col) = v0;
            *(float2*)(C + (size_t)(row + 8) * ldC + col) = v1;
        }
    }
#undef LOAD_TILE
}

__device__ __forceinline__ float hsig(float x) {
    return fminf(fmaxf(fmaf(0.2f, x, 0.5f), 0.f), 1.f);
}

// rh = hard_sigmoid(pre_r) * h_tm1    (r gate = weight cols 2048..4095)
__global__ void k_rh(const float* __restrict__ h,
                     const float* __restrict__ PreR, const float* __restrict__ PreI,
                     float* __restrict__ RH)
{
    int idx = blockIdx.x * blockDim.x + threadIdx.x;   // 1024*4096 threads
    int m  = idx >> 12;
    int j  = idx & 4095;
    int jj = j & 2047;
    float pre = (j < 2048) ? PreR[m * 4096 + 2048 + jj]
                           : PreI[m * 4096 + 2048 + jj];
    RH[idx] = hsig(pre) * h[idx];
}

// h_out = z*h + (1-z)*tanh(Xh + Hh)   (z gate = weight cols 0..2047)
__global__ void k_final(const float* __restrict__ h,
                        const float* __restrict__ PreR, const float* __restrict__ PreI,
                        const float* __restrict__ XhR,  const float* __restrict__ XhI,
                        const float* __restrict__ HhR,  const float* __restrict__ HhI,
                        float* __restrict__ out)
{
    int idx = blockIdx.x * blockDim.x + threadIdx.x;
    int m  = idx >> 12;
    int j  = idx & 4095;
    int jj = j & 2047;
    float zpre = (j < 2048) ? PreR[m * 4096 + jj] : PreI[m * 4096 + jj];
    float z = hsig(zpre);
    float hp = (j < 2048) ? (XhR[m * 2048 + jj] + HhR[m * 2048 + jj])
                          : (XhI[m * 2048 + jj] + HhI[m * 2048 + jj]);
    float hh = tanhf(hp);
    out[idx] = z * h[idx] + (1.f - z) * hh;
}

extern "C" void kernel_launch(void* const* d_in, const int* in_sizes, int n_in,
                              void* d_out, int out_size)
{
    const float* inputs = (const float*)d_in[0];
    const float* h      = (const float*)d_in[1];
    const float* rk     = (const float*)d_in[2];
    const float* ik     = (const float*)d_in[3];
    const float* rrk    = (const float*)d_in[4];
    const float* irk    = (const float*)d_in[5];
    const float* rb     = (const float*)d_in[6];
    const float* ib     = (const float*)d_in[7];
    float* out = (float*)d_out;

    float *PreR, *PreI, *XhR, *XhI, *HhR, *HhI, *RH;
    cudaGetSymbolAddress((void**)&PreR, g_PreR);
    cudaGetSymbolAddress((void**)&PreI, g_PreI);
    cudaGetSymbolAddress((void**)&XhR,  g_XhR);
    cudaGetSymbolAddress((void**)&XhI,  g_XhI);
    cudaGetSymbolAddress((void**)&HhR,  g_HhR);
    cudaGetSymbolAddress((void**)&HhI,  g_HhI);
    cudaGetSymbolAddress((void**)&RH,   g_RH);

    const int smemB = (2 * ASZ + 2 * BSZ) * 4;   // 71680 bytes
    cudaFuncSetAttribute(gemm_tf32, cudaFuncAttributeMaxDynamicSharedMemorySize, smemB);

    const unsigned NEG = 0x80000000u;
    dim3 blk(256);

    // phase 1: z,r gates, fused x + recurrent (K=8192), bias fused
    // real: [x1@Wr + x2@Wi + h1@Rr + h2@Ri]
    gemm_tf32<<<dim3(8, 32), blk, smemB>>>(inputs, h, rk, ik, rrk, irk,
                                           0u, 0u, 0u, 0u, 0, 256, rb, PreR, 4096);
    // imag: [-x1@Wi + x2@Wr - h1@Ri + h2@Rr]
    gemm_tf32<<<dim3(8, 32), blk, smemB>>>(inputs, h, ik, rk, irk, rrk,
                                           NEG, 0u, NEG, 0u, 0, 256, ib, PreI, 4096);
    // x_h (K=4096), weight cols 4096..6143
    gemm_tf32<<<dim3(8, 16), blk, smemB>>>(inputs, nullptr, rk, ik, rk, ik,
                                           0u, 0u, 0u, 0u, 4096, 128, rb + 4096, XhR, 2048);
    gemm_tf32<<<dim3(8, 16), blk, smemB>>>(inputs, nullptr, ik, rk, ik, rk,
                                           NEG, 0u, NEG, 0u, 4096, 128, ib + 4096, XhI, 2048);

    // r gate -> rh
    k_rh<<<16384, 256>>>(h, PreR, PreI, RH);

    // phase 2: (r*h) @ Rh
    gemm_tf32<<<dim3(8, 16), blk, smemB>>>(RH, nullptr, rrk, irk, rrk, irk,
                                           0u, 0u, 0u, 0u, 4096, 128, nullptr, HhR, 2048);
    gemm_tf32<<<dim3(8, 16), blk, smemB>>>(RH, nullptr, irk, rrk, irk, rrk,
                                           NEG, 0u, NEG, 0u, 4096, 128, nullptr, HhI, 2048);

    // gate combine
    k_final<<<16384, 256>>>(h, PreR, PreI, XhR, XhI, HhR, HhI, out);
}

// round 3
// speedup vs baseline: 1.0597x; 1.0597x over previous
#include <cuda_runtime.h>
#include <cstdint>

#define LDW 6144
#define NEGBIT 0x80000000u

// scratch (device globals; allocation in kernel_launch forbidden)
__device__ float g_PreR[1024 * 4096];
__device__ float g_PreI[1024 * 4096];
__device__ float g_XhR [1024 * 2048];
__device__ float g_XhI [1024 * 2048];
__device__ float g_HhR [1024 * 2048];
__device__ float g_HhI [1024 * 2048];
__device__ float g_RH  [1024 * 4096];

__device__ __forceinline__ unsigned f2tf(float x) {
    unsigned u; asm("cvt.rna.tf32.f32 %0, %1;" : "=r"(u) : "f"(x)); return u;
}
__device__ __forceinline__ uint32_t s2u(const void* p) {
    uint32_t a;
    asm("{ .reg .u64 t; cvta.to.shared.u64 t, %1; cvt.u32.u64 %0, t; }" : "=r"(a) : "l"(p));
    return a;
}

// SW128 swizzle on byte offset within a tile of 128B rows
#define SW(o) ((o) ^ (((o) >> 3) & 0x70))

#define LDSM4(r, a) \
    asm volatile("ldmatrix.sync.aligned.m8n8.x4.shared.b16 {%0,%1,%2,%3}, [%4];" \
        : "=r"((r)[0]), "=r"((r)[1]), "=r"((r)[2]), "=r"((r)[3]) : "r"(a))

#define MMA(acc, a, b0, b1) \
    asm volatile("mma.sync.aligned.m16n8k8.row.col.f32.tf32.tf32.f32 " \
        "{%0,%1,%2,%3},{%4,%5,%6,%7},{%8,%9},{%0,%1,%2,%3};" \
        : "+f"((acc)[0]), "+f"((acc)[1]), "+f"((acc)[2]), "+f"((acc)[3]) \
        : "r"((a)[0]), "r"((a)[1]), "r"((a)[2]), "r"((a)[3]), "r"(b0), "r"(b1))

// smem: 2 stages x (A 16KB + B 16KB)
#define STAGE   32768
#define SM_B_OFF 16384
#define SMEM_TOTAL (2 * STAGE)

// ---------------------------------------------------------------------------
// tf32 GEMM (mma.sync + ldmatrix): C[1024 x N] = A[1024 x K] @ Wsel (+bias)
// K split into 2048-row segments; seg -> weight matrix + sign by variant v:
//   v=0 (real): half0 -> W1 (+),  half1 -> W2 (+)
//   v=1 (imag): half0 -> W2 (-),  half1 -> W1 (+)
// blk = seg>>1 picks (W1a,W2a) vs (W1b,W2b). A rows k<4096 from A0 else A1.
// grid: x = m-tile (128 rows), y = n-tile*2 + v.
// ---------------------------------------------------------------------------
__global__ void __launch_bounds__(256, 1) gemm_tf32(
    const float* __restrict__ A0, const float* __restrict__ A1,
    const float* __restrict__ W1a, const float* __restrict__ W2a,
    const float* __restrict__ W1b, const float* __restrict__ W2b,
    int wcol0, int KT,
    const float* __restrict__ biasR, const float* __restrict__ biasI,
    float* __restrict__ CR, float* __restrict__ CI, int ldC)
{
    extern __shared__ char smem[];
    const uint32_t sb = s2u(smem);

    const int tid  = threadIdx.x;
    const int lane = tid & 31;
    const int warp = tid >> 5;
    const int wm   = warp >> 2;   // 0..1  (64-row warp tile)
    const int wn   = warp & 3;    // 0..3  (32-col warp tile)
    const int bm   = blockIdx.x;
    const int bn   = blockIdx.y >> 1;
    const int v    = blockIdx.y & 1;

    const float* bias = v ? biasI : biasR;
    float* C = v ? CI : CR;

    float acc[4][4][4];
    #pragma unroll
    for (int i = 0; i < 4; i++)
        #pragma unroll
        for (int j = 0; j < 4; j++)
            #pragma unroll
            for (int k = 0; k < 4; k++) acc[i][j][k] = 0.f;

    // ---- producer coords ----
    const int ar  = tid >> 3;          // A row 0..31 (+32i)
    const int ac4 = tid & 7;           // A 16B chunk
    const int bn2 = tid & 31;          // B n group: rows nb2*4..+3
    const int bk2 = tid >> 5;          // B k group: k rows bk2*4..+3
    const size_t mBase = (size_t)(bm * 128);
    const int    gn    = wcol0 + bn * 128;

    // ---- consumer (ldmatrix) per-lane constants ----
    const uint32_t xorv = (lane & 7) * 16;
    const uint32_t l87  = ((lane >> 3) & 1) * 8 + (lane & 7);
    const uint32_t p16  = (lane >> 4) * 16;
    const uint32_t aRow = (wm * 64 + l87) * 128;
    const uint32_t bRow = (wn * 32 + (lane & 7)) * 128;
    uint32_t aoff[4], boff[2];
    #pragma unroll
    for (int s = 0; s < 4; s++)  aoff[s]  = (s * 32 + p16) ^ xorv;
    #pragma unroll
    for (int sp = 0; sp < 2; sp++) boff[sp] = (sp * 64 + (lane >> 3) * 16) ^ xorv;

    float4 av0, av1, av2, av3, bv0, bv1, bv2, bv3;
    unsigned curSgn = 0, nextSgn = 0;

#define LOAD_TILE(KT_IDX)                                                           \
    do {                                                                            \
        const int kg = (KT_IDX) * 32;                                               \
        const float* Ap = (kg >= 4096) ? A1 : A0;                                   \
        const float* abase = Ap + mBase * 4096 + (kg & 4095);                       \
        av0 = *(const float4*)(abase + (size_t)(ar +  0) * 4096 + ac4 * 4);         \
        av1 = *(const float4*)(abase + (size_t)(ar + 32) * 4096 + ac4 * 4);         \
        av2 = *(const float4*)(abase + (size_t)(ar + 64) * 4096 + ac4 * 4);         \
        av3 = *(const float4*)(abase + (size_t)(ar + 96) * 4096 + ac4 * 4);         \
        const int seg = kg >> 11, blk = seg >> 1, half = seg & 1;                   \
        const float* W1 = blk ? W1b : W1a;                                          \
        const float* W2 = blk ? W2b : W2a;                                          \
        const float* Wp;                                                            \
        if (v == 0) { Wp = half ? W2 : W1; nextSgn = 0u; }                          \
        else        { Wp = half ? W1 : W2; nextSgn = half ? 0u : NEGBIT; }          \
        const float* bbase = Wp + (size_t)((kg & 2047) + bk2 * 4) * LDW + gn + bn2 * 4; \
        bv0 = *(const float4*)(bbase + 0 * LDW);                                    \
        bv1 = *(const float4*)(bbase + 1 * LDW);                                    \
        bv2 = *(const float4*)(bbase + 2 * LDW);                                    \
        bv3 = *(const float4*)(bbase + 3 * LDW);                                    \
    } while (0)

    LOAD_TILE(0);
    curSgn = nextSgn;

    for (int kt = 0; kt < KT; ++kt) {
        char* stg = smem + (kt & 1) * STAGE;
        const uint32_t sA = sb + (kt & 1) * STAGE;
        const uint32_t sB = sA + SM_B_OFF;

        // ---- STS: A rows (128B, SW128) ----
        {
            uint4 t;
            t.x = f2tf(av0.x); t.y = f2tf(av0.y); t.z = f2tf(av0.z); t.w = f2tf(av0.w);
            *(uint4*)(stg + SW((ar +  0) * 128 + ac4 * 16)) = t;
            t.x = f2tf(av1.x); t.y = f2tf(av1.y); t.z = f2tf(av1.z); t.w = f2tf(av1.w);
            *(uint4*)(stg + SW((ar + 32) * 128 + ac4 * 16)) = t;
            t.x = f2tf(av2.x); t.y = f2tf(av2.y); t.z = f2tf(av2.z); t.w = f2tf(av2.w);
            *(uint4*)(stg + SW((ar + 64) * 128 + ac4 * 16)) = t;
            t.x = f2tf(av3.x); t.y = f2tf(av3.y); t.z = f2tf(av3.z); t.w = f2tf(av3.w);
            *(uint4*)(stg + SW((ar + 96) * 128 + ac4 * 16)) = t;
        }
        // ---- STS: B transposed rows (n-major, 128B, SW128), sign applied ----
        {
            char* bstg = stg + SM_B_OFF;
            uint4 t;
            t.x = f2tf(bv0.x) ^ curSgn; t.y = f2tf(bv1.x) ^ curSgn;
            t.z = f2tf(bv2.x) ^ curSgn; t.w = f2tf(bv3.x) ^ curSgn;
            *(uint4*)(bstg + SW((bn2 * 4 + 0) * 128 + bk2 * 16)) = t;
            t.x = f2tf(bv0.y) ^ curSgn; t.y = f2tf(bv1.y) ^ curSgn;
            t.z = f2tf(bv2.y) ^ curSgn; t.w = f2tf(bv3.y) ^ curSgn;
            *(uint4*)(bstg + SW((bn2 * 4 + 1) * 128 + bk2 * 16)) = t;
            t.x = f2tf(bv0.z) ^ curSgn; t.y = f2tf(bv1.z) ^ curSgn;
            t.z = f2tf(bv2.z) ^ curSgn; t.w = f2tf(bv3.z) ^ curSgn;
            *(uint4*)(bstg + SW((bn2 * 4 + 2) * 128 + bk2 * 16)) = t;
            t.x = f2tf(bv0.w) ^ curSgn; t.y = f2tf(bv1.w) ^ curSgn;
            t.z = f2tf(bv2.w) ^ curSgn; t.w = f2tf(bv3.w) ^ curSgn;
            *(uint4*)(bstg + SW((bn2 * 4 + 3) * 128 + bk2 * 16)) = t;
        }
        __syncthreads();

        if (kt + 1 < KT) { LOAD_TILE(kt + 1); }

        // ---- MMA via ldmatrix fragments ----
        #pragma unroll
        for (int sp = 0; sp < 2; sp++) {
            uint32_t bfr[4][4];
            #pragma unroll
            for (int nf = 0; nf < 4; nf++)
                LDSM4(bfr[nf], sB + bRow + nf * (8 * 128) + boff[sp]);
            #pragma unroll
            for (int sh = 0; sh < 2; sh++) {
                const int s = sp * 2 + sh;
                uint32_t afr[4][4];
                #pragma unroll
                for (int mf = 0; mf < 4; mf++)
                    LDSM4(afr[mf], sA + aRow + mf * (16 * 128) + aoff[s]);
                #pragma unroll
                for (int mf = 0; mf < 4; mf++)
                    #pragma unroll
                    for (int nf = 0; nf < 4; nf++)
                        MMA(acc[mf][nf], afr[mf], bfr[nf][2 * sh], bfr[nf][2 * sh + 1]);
            }
        }
        curSgn = nextSgn;
    }

    // ---- epilogue ----
    const int gid = lane >> 2;
    const int tig = lane & 3;
    #pragma unroll
    for (int mf = 0; mf < 4; mf++) {
        const int row = bm * 128 + wm * 64 + mf * 16 + gid;
        #pragma unroll
        for (int nf = 0; nf < 4; nf++) {
            const int col = bn * 128 + wn * 32 + nf * 8 + tig * 2;
            float bb0 = 0.f, bb1 = 0.f;
            if (bias) { bb0 = bias[col]; bb1 = bias[col + 1]; }
            float2 v0 = make_float2(acc[mf][nf][0] + bb0, acc[mf][nf][1] + bb1);
            float2 v1 = make_float2(acc[mf][nf][2] + bb0, acc[mf][nf][3] + bb1);
            *(float2*)(C + (size_t)row       * ldC + col) = v0;
            *(float2*)(C + (size_t)(row + 8) * ldC + col) = v1;
        }
    }
#undef LOAD_TILE
}

// ---------------- elementwise ----------------
__device__ __forceinline__ float hsig(float x) {
    return fminf(fmaxf(fmaf(0.2f, x, 0.5f), 0.f), 1.f);
}

// rh = hard_sigmoid(pre_r) * h_tm1   (r gate = cols 2048..4095 of Pre)
__global__ void k_rh(const float* __restrict__ h,
                     const float* __restrict__ PreR, const float* __restrict__ PreI,
                     float* __restrict__ RH)
{
    int i4 = blockIdx.x * blockDim.x + threadIdx.x;   // 1M threads, 4 elems each
    int idx = i4 * 4;
    int m  = idx >> 12;
    int j  = idx & 4095;
    int jj = j & 2047;
    float4 pre = (j < 2048) ? *(const float4*)(PreR + m * 4096 + 2048 + jj)
                            : *(const float4*)(PreI + m * 4096 + 2048 + jj);
    float4 hv = *(const float4*)(h + idx);
    float4 o;
    o.x = hsig(pre.x) * hv.x;  o.y = hsig(pre.y) * hv.y;
    o.z = hsig(pre.z) * hv.z;  o.w = hsig(pre.w) * hv.w;
    *(float4*)(RH + idx) = o;
}

// h_out = z*h + (1-z)*tanh(Xh + Hh)  (z gate = cols 0..2047 of Pre)
__global__ void k_final(const float* __restrict__ h,
                        const float* __restrict__ PreR, const float* __restrict__ PreI,
                        const float* __restrict__ XhR,  const float* __restrict__ XhI,
                        const float* __restrict__ HhR,  const float* __restrict__ HhI,
                        float* __restrict__ out)
{
    int i4 = blockIdx.x * blockDim.x + threadIdx.x;
    int idx = i4 * 4;
    int m  = idx >> 12;
    int j  = idx & 4095;
    int jj = j & 2047;
    float4 zp, xh, hh4;
    if (j < 2048) {
        zp  = *(const float4*)(PreR + m * 4096 + jj);
        xh  = *(const float4*)(XhR + m * 2048 + jj);
        hh4 = *(const float4*)(HhR + m * 2048 + jj);
    } else {
        zp  = *(const float4*)(PreI + m * 4096 + jj);
        xh  = *(const float4*)(XhI + m * 2048 + jj);
        hh4 = *(const float4*)(HhI + m * 2048 + jj);
    }
    float4 hv = *(const float4*)(h + idx);
    float4 o;
    float z, t;
    z = hsig(zp.x); t = tanhf(xh.x + hh4.x); o.x = z * hv.x + (1.f - z) * t;
    z = hsig(zp.y); t = tanhf(xh.y + hh4.y); o.y = z * hv.y + (1.f - z) * t;
    z = hsig(zp.z); t = tanhf(xh.z + hh4.z); o.z = z * hv.z + (1.f - z) * t;
    z = hsig(zp.w); t = tanhf(xh.w + hh4.w); o.w = z * hv.w + (1.f - z) * t;
    *(float4*)(out + idx) = o;
}

// ---------------- launch ----------------
extern "C" void kernel_launch(void* const* d_in, const int* in_sizes, int n_in,
                              void* d_out, int out_size)
{
    const float* inputs = (const float*)d_in[0];
    const float* h      = (const float*)d_in[1];
    const float* rk     = (const float*)d_in[2];
    const float* ik     = (const float*)d_in[3];
    const float* rrk    = (const float*)d_in[4];
    const float* irk    = (const float*)d_in[5];
    const float* rb     = (const float*)d_in[6];
    const float* ib     = (const float*)d_in[7];
    float* out = (float*)d_out;

    float *PreR, *PreI, *XhR, *XhI, *HhR, *HhI, *RH;
    cudaGetSymbolAddress((void**)&PreR, g_PreR);
    cudaGetSymbolAddress((void**)&PreI, g_PreI);
    cudaGetSymbolAddress((void**)&XhR,  g_XhR);
    cudaGetSymbolAddress((void**)&XhI,  g_XhI);
    cudaGetSymbolAddress((void**)&HhR,  g_HhR);
    cudaGetSymbolAddress((void**)&HhI,  g_HhI);
    cudaGetSymbolAddress((void**)&RH,   g_RH);

    cudaFuncSetAttribute(gemm_tf32, cudaFuncAttributeMaxDynamicSharedMemorySize, SMEM_TOTAL);
    dim3 blk(256);

    // Pre (z,r): K=8192 ([x|h]), weight cols 0..4095, bias, C=[1024,4096]
    gemm_tf32<<<dim3(8, 64), blk, SMEM_TOTAL>>>(
        inputs, h, rk, ik, rrk, irk, 0, 256, rb, ib, PreR, PreI, 4096);

    // Xh: K=4096 (x), weight cols 4096..6143, bias+4096
    gemm_tf32<<<dim3(8, 32), blk, SMEM_TOTAL>>>(
        inputs, nullptr, rk, ik, rk, ik, 4096, 128,
        rb + 4096, ib + 4096, XhR, XhI, 2048);

    // rh = hard_sigmoid(pre_r) * h
    k_rh<<<4096, 256>>>(h, PreR, PreI, RH);

    // Hh: K=4096 (rh), recurrent cols 4096..6143, no bias
    gemm_tf32<<<dim3(8, 32), blk, SMEM_TOTAL>>>(
        RH, nullptr, rrk, irk, rrk, irk, 4096, 128,
        nullptr, nullptr, HhR, HhI, 2048);

    // combine
    k_final<<<4096, 256>>>(h, PreR, PreI, XhR, XhI, HhR, HhI, out);
}